// round 3
// baseline (speedup 1.0000x reference)
#include <cuda_runtime.h>
#include <cuda_fp16.h>
#include <cstdint>

#define BN 524288
#define NLEV 16
#define LTBL (1 << 19)
#define TMASK (LTBL - 1)
#define CN 4
#define NBLK 3

// ---------------- device-global scratch (no allocations allowed) ----------------
__device__ __align__(16) unsigned g_enc[(size_t)BN * 16];   // [p][l] half2 {f0,f1}
__device__ int g_sorted[BN + 256];
__device__ int g_cnt[CN], g_fill[CN], g_astart[CN + 1];
__device__ __align__(16) uint2 g_W0F[4 * 2 * 8 * 4 * 32];        // 8192  fragmentized W0
__device__ __align__(16) uint2 g_WrF[4 * 3 * 16 * 8 * 4 * 32];   // 196608 fragmentized Wres

__constant__ float c_res[16]  = {16.f,20.f,25.f,32.f,40.f,50.f,64.f,80.f,
                                 101.f,128.f,161.f,203.f,256.f,322.f,406.f,512.f};
__constant__ float c_grid[16] = {1.f/16.f,1.f/20.f,1.f/25.f,1.f/32.f,1.f/40.f,1.f/50.f,
                                 1.f/64.f,1.f/80.f,1.f/101.f,1.f/128.f,1.f/161.f,1.f/203.f,
                                 1.f/256.f,1.f/322.f,1.f/406.f,1.f/512.f};
__constant__ unsigned c_prime[6] = {1u,2654435761u,805459861u,3674653429u,2097192037u,1434869437u};

// ---------------- small setup kernels ----------------
__global__ void zero_kernel() {
    if (threadIdx.x < CN) { g_cnt[threadIdx.x] = 0; g_fill[threadIdx.x] = 0; }
}

__global__ void hist_kernel(const int* __restrict__ lid) {
    __shared__ int sh[CN];
    int tid = threadIdx.x;
    if (tid < CN) sh[tid] = 0;
    __syncthreads();
    int i = blockIdx.x * 256 + tid;
    atomicAdd(&sh[lid[i] & 3], 1);
    __syncthreads();
    if (tid < CN) atomicAdd(&g_cnt[tid], sh[tid]);
}

__global__ void starts_kernel() {
    int s = 0;
    for (int c = 0; c < CN; c++) { g_astart[c] = s; s += (g_cnt[c] + 63) & ~63; }
    g_astart[CN] = s;
}

__global__ void pad_kernel() {
    int i = blockIdx.x * 256 + threadIdx.x;
    if (i < BN + 256) g_sorted[i] = (int)0x80000000;
}

__global__ void scatter_kernel(const int* __restrict__ lid) {
    __shared__ int scnt[CN], sbase[CN];
    int tid = threadIdx.x;
    if (tid < CN) scnt[tid] = 0;
    __syncthreads();
    int i = blockIdx.x * 256 + tid;
    int c = lid[i] & 3;
    int r = atomicAdd(&scnt[c], 1);
    __syncthreads();
    if (tid < CN) sbase[tid] = atomicAdd(&g_fill[tid], scnt[tid]);
    __syncthreads();
    g_sorted[g_astart[c] + sbase[c] + r] = i;
}

// ---------------- weight fragmentizer ----------------
// B-fragment for mma.m16n8k16 (col-major KxN): lane l (gid=l>>2, tig=l&3):
//   reg0 = {W[k0][n], W[k0+1][n]},  reg1 = {W[k0+8][n], W[k0+9][n]},  k0 = kc*16 + tig*2, n = slice col.
__global__ void __launch_bounds__(256) prep_kernel(const float* __restrict__ W0,
                                                   const float* __restrict__ Wres) {
    int id = blockIdx.x * 256 + threadIdx.x;
    const int NWR = 4 * 3 * 16 * 8 * 4 * 32;
    const int NW0 = 4 * 2 * 8 * 4 * 32;
    if (id < NWR) {
        int lane = id & 31; int r = id >> 5;
        int nt = r & 3; r >>= 2;
        int wv = r & 7; r >>= 3;
        int kc = r & 15; r >>= 4;
        int l = r % 3; int c = r / 3;
        int n  = wv * 32 + nt * 8 + (lane >> 2);
        int k0 = kc * 16 + (lane & 3) * 2;
        const float* Wb = Wres + (size_t)(c * 3 + l) * 256 * 256;
        __half2 lo = __floats2half2_rn(Wb[k0 * 256 + n],       Wb[(k0 + 1) * 256 + n]);
        __half2 hi = __floats2half2_rn(Wb[(k0 + 8) * 256 + n], Wb[(k0 + 9) * 256 + n]);
        g_WrF[id] = make_uint2(*(unsigned*)&lo, *(unsigned*)&hi);
    } else if (id < NWR + NW0) {
        int id2 = id - NWR;
        int lane = id2 & 31; int r = id2 >> 5;
        int nt = r & 3; r >>= 2;
        int wv = r & 7; r >>= 3;
        int kc = r & 1; r >>= 1;
        int c = r;
        int n  = wv * 32 + nt * 8 + (lane >> 2);
        int k0 = kc * 16 + (lane & 3) * 2;
        const float* Wb = W0 + (size_t)c * 32 * 256;
        __half2 lo = __floats2half2_rn(Wb[k0 * 256 + n],       Wb[(k0 + 1) * 256 + n]);
        __half2 hi = __floats2half2_rn(Wb[(k0 + 8) * 256 + n], Wb[(k0 + 9) * 256 + n]);
        g_W0F[id2] = make_uint2(*(unsigned*)&lo, *(unsigned*)&hi);
    }
}

// ---------------- hash encoding ----------------
// corner i (0..63): hash offset dim d uses bit (5-d) of i; weight dim d uses bit d of i.
// split i = 8a + b:  hash = HA[a]^HB[b] (HA: dims 0-2 from a bits 2..0, HB: dims 3-5 from b bits 2..0)
//                    weight = WA[a]*WB[b] (WA: dims 3-5 from a bits 0..2, WB: dims 0-2 from b bits 0..2)
__global__ void __launch_bounds__(256) encode_kernel(const float* __restrict__ x,
                                                     const float* __restrict__ emb) {
    int l = blockIdx.x >> 11;                    // 2048 blocks per level -> level uniform per block
    int p = ((blockIdx.x & 2047) << 8) + threadIdx.x;
    const float2* __restrict__ tab = reinterpret_cast<const float2*>(emb) + (size_t)l * LTBL;
    float res = c_res[l], grid = c_grid[l];

    float wp[6]; unsigned u0[6], u1[6];
#pragma unroll
    for (int d = 0; d < 6; d++) {
        float xd = x[p * 6 + d];
        xd = fminf(fmaxf(xd, 0.f), 1.f);
        float f = floorf(xd * res);
        int bl = (int)f;
        float w = (xd - f * grid) / (grid + 1e-6f);
        wp[d] = fminf(fmaxf(w, 0.f), 1.f);
        u0[d] = (unsigned)bl * c_prime[d];
        u1[d] = u0[d] + c_prime[d];
    }
    unsigned HA[8], HB[8]; float WA[8], WB[8];
#pragma unroll
    for (int a = 0; a < 8; a++) {
        HA[a] = ((a & 4) ? u1[0] : u0[0]) ^ ((a & 2) ? u1[1] : u0[1]) ^ ((a & 1) ? u1[2] : u0[2]);
        WA[a] = ((a & 1) ? wp[3] : 1.f - wp[3]) * ((a & 2) ? wp[4] : 1.f - wp[4]) * ((a & 4) ? wp[5] : 1.f - wp[5]);
        HB[a] = ((a & 4) ? u1[3] : u0[3]) ^ ((a & 2) ? u1[4] : u0[4]) ^ ((a & 1) ? u1[5] : u0[5]);
        WB[a] = ((a & 1) ? wp[0] : 1.f - wp[0]) * ((a & 2) ? wp[1] : 1.f - wp[1]) * ((a & 4) ? wp[2] : 1.f - wp[2]);
    }
    float f0 = 0.f, f1 = 0.f;
#pragma unroll
    for (int a = 0; a < 8; a++) {
        unsigned ha = HA[a]; float wa = WA[a];
#pragma unroll
        for (int b = 0; b < 8; b++) {
            float2 e = __ldg(&tab[(ha ^ HB[b]) & TMASK]);
            float w = wa * WB[b];
            f0 += w * e.x;
            f1 += w * e.y;
        }
    }
    __half2 h = __floats2half2_rn(f0, f1);
    g_enc[(size_t)p * 16 + l] = *reinterpret_cast<unsigned*>(&h);
}

// ---------------- MMA helpers ----------------
__device__ __forceinline__ void ldmA(unsigned a[4], unsigned addr) {
    asm volatile("ldmatrix.sync.aligned.m8n8.x4.shared.b16 {%0,%1,%2,%3}, [%4];"
                 : "=r"(a[0]), "=r"(a[1]), "=r"(a[2]), "=r"(a[3]) : "r"(addr));
}
__device__ __forceinline__ void mma16816(float c[4], const unsigned a[4], unsigned b0, unsigned b1) {
    asm volatile("mma.sync.aligned.m16n8k16.row.col.f32.f16.f16.f32 "
                 "{%0,%1,%2,%3},{%4,%5,%6,%7},{%8,%9},{%0,%1,%2,%3};"
                 : "+f"(c[0]), "+f"(c[1]), "+f"(c[2]), "+f"(c[3])
                 : "r"(a[0]), "r"(a[1]), "r"(a[2]), "r"(a[3]), "r"(b0), "r"(b1));
}

// ---------------- fused MLP: one 64-point single-class tile per block ----------------
__global__ void __launch_bounds__(256, 1) mlp_kernel(
    const float* __restrict__ b0, const float* __restrict__ bres,
    const float* __restrict__ scales, const float* __restrict__ Wout,
    const float* __restrict__ bout, float* __restrict__ out)
{
    __shared__ __align__(16) __half hbuf[64 * 256];   // 32KB, swizzled: chunk' = chunk ^ (row&7)
    __shared__ float sB0[256], sBres[3][256], sWout[256], sScale[3];
    __shared__ float souts[64];
    __shared__ int sidx[64];

    int t = blockIdx.x;
    if (t * 64 >= g_astart[CN]) return;
    int c = 0;
#pragma unroll
    for (int i = 0; i < CN - 1; i++) if (t * 64 >= g_astart[i + 1]) c = i + 1;

    int tid = threadIdx.x;
    int w = tid >> 5, lane = tid & 31;
    int g = lane >> 2, tig = lane & 3;
    int mat = lane >> 3, rowin = lane & 7;
    int wbase = w * 32;

    sB0[tid]      = b0[c * 256 + tid];
    sBres[0][tid] = bres[(c * 3 + 0) * 256 + tid];
    sBres[1][tid] = bres[(c * 3 + 1) * 256 + tid];
    sBres[2][tid] = bres[(c * 3 + 2) * 256 + tid];
    sWout[tid]    = Wout[c * 256 + tid];
    if (tid < 3)  sScale[tid] = scales[c * 3 + tid];
    if (tid < 64) { sidx[tid] = g_sorted[t * 64 + tid]; souts[tid] = 0.f; }
    __syncthreads();

    // stage encoding tile (64 x 32 halves) into hbuf, swizzled
    {
        int r = tid >> 2, cc = tid & 3;
        int j = sidx[r] & 0x7fffffff;   // pad slots (INT_MIN) -> point 0, compute wasted, store masked
        uint4 v = *reinterpret_cast<const uint4*>(&g_enc[(size_t)j * 16 + cc * 4]);
        *reinterpret_cast<uint4*>(&hbuf[r * 256 + ((cc ^ (r & 7)) << 3)]) = v;
    }
    __syncthreads();

    unsigned hb32 = (unsigned)__cvta_generic_to_shared(hbuf);
    unsigned* hbu = reinterpret_cast<unsigned*>(hbuf);

    float acc[4][4][4];
    float hres[4][4][4];

    // ---- layer 0: enc[64x32] @ W0[32x256] ----
#pragma unroll
    for (int mt = 0; mt < 4; mt++)
#pragma unroll
        for (int nt = 0; nt < 4; nt++)
#pragma unroll
            for (int e = 0; e < 4; e++) acc[mt][nt][e] = 0.f;
#pragma unroll
    for (int kc = 0; kc < 2; kc++) {
        unsigned af[4][4];
#pragma unroll
        for (int mt = 0; mt < 4; mt++) {
            int row = mt * 16 + ((mat & 1) << 3) + rowin;
            int cc  = (kc << 1) + (mat >> 1);
            ldmA(af[mt], hb32 + row * 512 + ((cc ^ (row & 7)) << 4));
        }
        uint2 bf[4];
#pragma unroll
        for (int nt = 0; nt < 4; nt++)
            bf[nt] = g_W0F[(((c * 2 + kc) * 8 + w) * 4 + nt) * 32 + lane];
#pragma unroll
        for (int mt = 0; mt < 4; mt++)
#pragma unroll
            for (int nt = 0; nt < 4; nt++)
                mma16816(acc[mt][nt], af[mt], bf[nt].x, bf[nt].y);
    }
#pragma unroll
    for (int mt = 0; mt < 4; mt++)
#pragma unroll
        for (int nt = 0; nt < 4; nt++) {
            int n0 = wbase + nt * 8 + tig * 2;
            hres[mt][nt][0] = fmaxf(acc[mt][nt][0] + sB0[n0], 0.f);
            hres[mt][nt][1] = fmaxf(acc[mt][nt][1] + sB0[n0 + 1], 0.f);
            hres[mt][nt][2] = fmaxf(acc[mt][nt][2] + sB0[n0], 0.f);
            hres[mt][nt][3] = fmaxf(acc[mt][nt][3] + sB0[n0 + 1], 0.f);
        }
    __syncthreads();   // all reads of enc tile done
    // write h1 (fp16) to hbuf
#pragma unroll
    for (int mt = 0; mt < 4; mt++)
#pragma unroll
        for (int nt = 0; nt < 4; nt++) {
            int row0 = mt * 16 + g, row1 = row0 + 8;
            int ccw = (wbase >> 3) + nt;
            __half2 p0 = __floats2half2_rn(hres[mt][nt][0], hres[mt][nt][1]);
            __half2 p1 = __floats2half2_rn(hres[mt][nt][2], hres[mt][nt][3]);
            hbu[row0 * 128 + ((ccw ^ (row0 & 7)) << 2) + tig] = *(unsigned*)&p0;
            hbu[row1 * 128 + ((ccw ^ (row1 & 7)) << 2) + tig] = *(unsigned*)&p1;
        }
    __syncthreads();

    // ---- residual blocks ----
#pragma unroll
    for (int li = 0; li < 3; li++) {
#pragma unroll
        for (int mt = 0; mt < 4; mt++)
#pragma unroll
            for (int nt = 0; nt < 4; nt++)
#pragma unroll
                for (int e = 0; e < 4; e++) acc[mt][nt][e] = 0.f;
#pragma unroll
        for (int kc = 0; kc < 16; kc++) {
            unsigned af[4][4];
#pragma unroll
            for (int mt = 0; mt < 4; mt++) {
                int row = mt * 16 + ((mat & 1) << 3) + rowin;
                int cc  = (kc << 1) + (mat >> 1);
                ldmA(af[mt], hb32 + row * 512 + ((cc ^ (row & 7)) << 4));
            }
            uint2 bf[4];
#pragma unroll
            for (int nt = 0; nt < 4; nt++)
                bf[nt] = g_WrF[((((c * 3 + li) * 16 + kc) * 8 + w) * 4 + nt) * 32 + lane];
#pragma unroll
            for (int mt = 0; mt < 4; mt++)
#pragma unroll
                for (int nt = 0; nt < 4; nt++)
                    mma16816(acc[mt][nt], af[mt], bf[nt].x, bf[nt].y);
        }
        float sc = sScale[li];
#pragma unroll
        for (int mt = 0; mt < 4; mt++)
#pragma unroll
            for (int nt = 0; nt < 4; nt++) {
                int n0 = wbase + nt * 8 + tig * 2;
                hres[mt][nt][0] = sc * fmaxf(acc[mt][nt][0] + sBres[li][n0], 0.f) + hres[mt][nt][0];
                hres[mt][nt][1] = sc * fmaxf(acc[mt][nt][1] + sBres[li][n0 + 1], 0.f) + hres[mt][nt][1];
                hres[mt][nt][2] = sc * fmaxf(acc[mt][nt][2] + sBres[li][n0], 0.f) + hres[mt][nt][2];
                hres[mt][nt][3] = sc * fmaxf(acc[mt][nt][3] + sBres[li][n0 + 1], 0.f) + hres[mt][nt][3];
            }
        if (li < 2) {
            __syncthreads();
#pragma unroll
            for (int mt = 0; mt < 4; mt++)
#pragma unroll
                for (int nt = 0; nt < 4; nt++) {
                    int row0 = mt * 16 + g, row1 = row0 + 8;
                    int ccw = (wbase >> 3) + nt;
                    __half2 p0 = __floats2half2_rn(hres[mt][nt][0], hres[mt][nt][1]);
                    __half2 p1 = __floats2half2_rn(hres[mt][nt][2], hres[mt][nt][3]);
                    hbu[row0 * 128 + ((ccw ^ (row0 & 7)) << 2) + tig] = *(unsigned*)&p0;
                    hbu[row1 * 128 + ((ccw ^ (row1 & 7)) << 2) + tig] = *(unsigned*)&p1;
                }
            __syncthreads();
        }
    }

    // ---- output layer: out = h @ Wout + bout ----
#pragma unroll
    for (int mt = 0; mt < 4; mt++) {
        float sA = 0.f, sB2 = 0.f;
#pragma unroll
        for (int nt = 0; nt < 4; nt++) {
            int n0 = wbase + nt * 8 + tig * 2;
            sA  += hres[mt][nt][0] * sWout[n0] + hres[mt][nt][1] * sWout[n0 + 1];
            sB2 += hres[mt][nt][2] * sWout[n0] + hres[mt][nt][3] * sWout[n0 + 1];
        }
        sA  += __shfl_xor_sync(0xffffffffu, sA, 1);
        sA  += __shfl_xor_sync(0xffffffffu, sA, 2);
        sB2 += __shfl_xor_sync(0xffffffffu, sB2, 1);
        sB2 += __shfl_xor_sync(0xffffffffu, sB2, 2);
        if (tig == 0) {
            atomicAdd(&souts[mt * 16 + g], sA);
            atomicAdd(&souts[mt * 16 + 8 + g], sB2);
        }
    }
    __syncthreads();
    if (tid < 64) {
        int id = sidx[tid];
        if (id >= 0) out[id] = souts[tid] + bout[c];
    }
}

// ---------------- launch ----------------
extern "C" void kernel_launch(void* const* d_in, const int* in_sizes, int n_in,
                              void* d_out, int out_size) {
    const float* x      = (const float*)d_in[0];
    const int*   lid    = (const int*)d_in[1];
    const float* emb    = (const float*)d_in[2];
    const float* W0     = (const float*)d_in[3];
    const float* b0     = (const float*)d_in[4];
    const float* Wres   = (const float*)d_in[5];
    const float* bres   = (const float*)d_in[6];
    const float* scales = (const float*)d_in[7];
    const float* Wout   = (const float*)d_in[8];
    const float* bout   = (const float*)d_in[9];
    float* out = (float*)d_out;

    zero_kernel<<<1, 32>>>();
    hist_kernel<<<BN / 256, 256>>>(lid);
    starts_kernel<<<1, 1>>>();
    pad_kernel<<<(BN + 256 + 255) / 256, 256>>>();
    scatter_kernel<<<BN / 256, 256>>>(lid);
    prep_kernel<<<800, 256>>>(W0, Wres);
    encode_kernel<<<NLEV * (BN / 256), 256>>>(x, emb);
    mlp_kernel<<<BN / 64 + CN, 256>>>(b0, bres, scales, Wout, bout, out);
}

// round 5
// speedup vs baseline: 1.3068x; 1.3068x over previous
#include <cuda_runtime.h>
#include <cuda_fp16.h>
#include <cstdint>

#define BN 524288
#define NLEV 16
#define LTBL (1 << 19)
#define TMASK (LTBL - 1)
#define CN 4
#define NBLK 3

// ---------------- device-global scratch (no allocations allowed) ----------------
__device__ __align__(16) unsigned g_enc[(size_t)BN * 16];   // [p][l] half2 {f0,f1}
__device__ int g_sorted[BN + 256];
__device__ int g_cnt[CN], g_fill[CN], g_astart[CN + 1];
__device__ __align__(16) uint2 g_W0F[4 * 2 * 8 * 4 * 32];        // 8192  fragmentized W0
__device__ __align__(16) uint2 g_WrF[4 * 3 * 16 * 8 * 4 * 32];   // 196608 fragmentized Wres

__constant__ float c_res[16]  = {16.f,20.f,25.f,32.f,40.f,50.f,64.f,80.f,
                                 101.f,128.f,161.f,203.f,256.f,322.f,406.f,512.f};
__constant__ float c_grid[16] = {1.f/16.f,1.f/20.f,1.f/25.f,1.f/32.f,1.f/40.f,1.f/50.f,
                                 1.f/64.f,1.f/80.f,1.f/101.f,1.f/128.f,1.f/161.f,1.f/203.f,
                                 1.f/256.f,1.f/322.f,1.f/406.f,1.f/512.f};
__constant__ unsigned c_prime[6] = {1u,2654435761u,805459861u,3674653429u,2097192037u,1434869437u};

// ---------------- small setup kernels ----------------
__global__ void zero_kernel() {
    if (threadIdx.x < CN) { g_cnt[threadIdx.x] = 0; g_fill[threadIdx.x] = 0; }
}

__global__ void hist_kernel(const int* __restrict__ lid) {
    __shared__ int sh[CN];
    int tid = threadIdx.x;
    if (tid < CN) sh[tid] = 0;
    __syncthreads();
    int i = blockIdx.x * 256 + tid;
    atomicAdd(&sh[lid[i] & 3], 1);
    __syncthreads();
    if (tid < CN) atomicAdd(&g_cnt[tid], sh[tid]);
}

__global__ void starts_kernel() {
    int s = 0;
    for (int c = 0; c < CN; c++) { g_astart[c] = s; s += (g_cnt[c] + 63) & ~63; }
    g_astart[CN] = s;
}

__global__ void pad_kernel() {
    int i = blockIdx.x * 256 + threadIdx.x;
    if (i < BN + 256) g_sorted[i] = (int)0x80000000;
}

__global__ void scatter_kernel(const int* __restrict__ lid) {
    __shared__ int scnt[CN], sbase[CN];
    int tid = threadIdx.x;
    if (tid < CN) scnt[tid] = 0;
    __syncthreads();
    int i = blockIdx.x * 256 + tid;
    int c = lid[i] & 3;
    int r = atomicAdd(&scnt[c], 1);
    __syncthreads();
    if (tid < CN) sbase[tid] = atomicAdd(&g_fill[tid], scnt[tid]);
    __syncthreads();
    g_sorted[g_astart[c] + sbase[c] + r] = i;
}

// ---------------- weight fragmentizer ----------------
__global__ void __launch_bounds__(256) prep_kernel(const float* __restrict__ W0,
                                                   const float* __restrict__ Wres) {
    int id = blockIdx.x * 256 + threadIdx.x;
    const int NWR = 4 * 3 * 16 * 8 * 4 * 32;
    const int NW0 = 4 * 2 * 8 * 4 * 32;
    if (id < NWR) {
        int lane = id & 31; int r = id >> 5;
        int nt = r & 3; r >>= 2;
        int wv = r & 7; r >>= 3;
        int kc = r & 15; r >>= 4;
        int l = r % 3; int c = r / 3;
        int n  = wv * 32 + nt * 8 + (lane >> 2);
        int k0 = kc * 16 + (lane & 3) * 2;
        const float* Wb = Wres + (size_t)(c * 3 + l) * 256 * 256;
        __half2 lo = __floats2half2_rn(Wb[k0 * 256 + n],       Wb[(k0 + 1) * 256 + n]);
        __half2 hi = __floats2half2_rn(Wb[(k0 + 8) * 256 + n], Wb[(k0 + 9) * 256 + n]);
        g_WrF[id] = make_uint2(*(unsigned*)&lo, *(unsigned*)&hi);
    } else if (id < NWR + NW0) {
        int id2 = id - NWR;
        int lane = id2 & 31; int r = id2 >> 5;
        int nt = r & 3; r >>= 2;
        int wv = r & 7; r >>= 3;
        int kc = r & 1; r >>= 1;
        int c = r;
        int n  = wv * 32 + nt * 8 + (lane >> 2);
        int k0 = kc * 16 + (lane & 3) * 2;
        const float* Wb = W0 + (size_t)c * 32 * 256;
        __half2 lo = __floats2half2_rn(Wb[k0 * 256 + n],       Wb[(k0 + 1) * 256 + n]);
        __half2 hi = __floats2half2_rn(Wb[(k0 + 8) * 256 + n], Wb[(k0 + 9) * 256 + n]);
        g_W0F[id2] = make_uint2(*(unsigned*)&lo, *(unsigned*)&hi);
    }
}

// ---------------- hash encoding with dim-0 pair merging ----------------
// Corner i (bit j of i): hash dim d uses bit (5-d); weight dim d uses bit d.
//   pair bit  = b5  : hash dim 0 (prime=1, offsets bl0 / bl0+1), weight dim 5
//   group A   = b4,b3: hash dims 1,2; weight dims 4,3   (4 combos)
//   group B   = b2..b0: hash dims 3,4,5; weight dims 2,1,0  (8 combos)
// If bl0 even: pair hashes = h, h^1 -> adjacent float2 entries -> one LDG.128.
__global__ void __launch_bounds__(256) encode_kernel(const float* __restrict__ x,
                                                     const float* __restrict__ emb) {
    int l = blockIdx.x >> 11;                    // 2048 blocks per level
    int p = ((blockIdx.x & 2047) << 8) + threadIdx.x;
    const float2* __restrict__ tab  = reinterpret_cast<const float2*>(emb) + (size_t)l * LTBL;
    const float4* __restrict__ tab4 = reinterpret_cast<const float4*>(emb + (size_t)l * LTBL * 2);
    float res = c_res[l], grid = c_grid[l];

    float wp[6]; unsigned u0[6], u1[6];
#pragma unroll
    for (int d = 0; d < 6; d++) {
        float xd = x[p * 6 + d];
        xd = fminf(fmaxf(xd, 0.f), 1.f);
        float f = floorf(xd * res);
        int bl = (int)f;
        float w = (xd - f * grid) / (grid + 1e-6f);
        wp[d] = fminf(fmaxf(w, 0.f), 1.f);
        u0[d] = (unsigned)bl * c_prime[d];
        u1[d] = u0[d] + c_prime[d];
    }
    unsigned HA2[4], HB[8]; float WA2[4], WB[8];
#pragma unroll
    for (int a = 0; a < 4; a++) {
        HA2[a] = ((a & 2) ? u1[1] : u0[1]) ^ ((a & 1) ? u1[2] : u0[2]);
        WA2[a] = ((a & 2) ? wp[4] : 1.f - wp[4]) * ((a & 1) ? wp[3] : 1.f - wp[3]);
    }
#pragma unroll
    for (int b = 0; b < 8; b++) {
        HB[b] = ((b & 4) ? u1[3] : u0[3]) ^ ((b & 2) ? u1[4] : u0[4]) ^ ((b & 1) ? u1[5] : u0[5]);
        WB[b] = ((b & 4) ? wp[2] : 1.f - wp[2]) * ((b & 2) ? wp[1] : 1.f - wp[1]) * ((b & 1) ? wp[0] : 1.f - wp[0]);
    }
    float w5 = wp[5], om5 = 1.f - wp[5];
    float f0 = 0.f, f1 = 0.f;

    if ((u0[0] & 1u) == 0u) {
        // even bl0: merged pair loads (one float4 per pair)
#pragma unroll
        for (int a = 0; a < 4; a++) {
            unsigned ra = u0[0] ^ HA2[a]; float wa = WA2[a];
#pragma unroll
            for (int b = 0; b < 8; b++) {
                unsigned h0 = (ra ^ HB[b]) & TMASK;
                float4 v = __ldg(&tab4[h0 >> 1]);
                float e0x, e0y, e1x, e1y;
                if (h0 & 1u) { e0x = v.z; e0y = v.w; e1x = v.x; e1y = v.y; }
                else         { e0x = v.x; e0y = v.y; e1x = v.z; e1y = v.w; }
                float w  = wa * WB[b];
                float wA = w * om5, wB2 = w * w5;
                f0 += wA * e0x; f0 += wB2 * e1x;
                f1 += wA * e0y; f1 += wB2 * e1y;
            }
        }
    } else {
        // odd bl0: two separate loads per pair
#pragma unroll
        for (int a = 0; a < 4; a++) {
            unsigned ra0 = u0[0] ^ HA2[a];
            unsigned ra1 = u1[0] ^ HA2[a];
            float wa = WA2[a];
#pragma unroll
            for (int b = 0; b < 8; b++) {
                float2 e0 = __ldg(&tab[(ra0 ^ HB[b]) & TMASK]);
                float2 e1 = __ldg(&tab[(ra1 ^ HB[b]) & TMASK]);
                float w  = wa * WB[b];
                float wA = w * om5, wB2 = w * w5;
                f0 += wA * e0.x; f0 += wB2 * e1.x;
                f1 += wA * e0.y; f1 += wB2 * e1.y;
            }
        }
    }
    __half2 h = __floats2half2_rn(f0, f1);
    g_enc[(size_t)p * 16 + l] = *reinterpret_cast<unsigned*>(&h);
}

// ---------------- MMA helpers ----------------
__device__ __forceinline__ void ldmA(unsigned a[4], unsigned addr) {
    asm volatile("ldmatrix.sync.aligned.m8n8.x4.shared.b16 {%0,%1,%2,%3}, [%4];"
                 : "=r"(a[0]), "=r"(a[1]), "=r"(a[2]), "=r"(a[3]) : "r"(addr));
}
__device__ __forceinline__ void mma16816(float c[4], const unsigned a[4], unsigned b0, unsigned b1) {
    asm volatile("mma.sync.aligned.m16n8k16.row.col.f32.f16.f16.f32 "
                 "{%0,%1,%2,%3},{%4,%5,%6,%7},{%8,%9},{%0,%1,%2,%3};"
                 : "+f"(c[0]), "+f"(c[1]), "+f"(c[2]), "+f"(c[3])
                 : "r"(a[0]), "r"(a[1]), "r"(a[2]), "r"(a[3]), "r"(b0), "r"(b1));
}

// ---------------- fused MLP: one 64-point single-class tile per block ----------------
__global__ void __launch_bounds__(256, 1) mlp_kernel(
    const float* __restrict__ b0, const float* __restrict__ bres,
    const float* __restrict__ scales, const float* __restrict__ Wout,
    const float* __restrict__ bout, float* __restrict__ out)
{
    __shared__ __align__(16) __half hbuf[64 * 256];   // 32KB, swizzled: chunk' = chunk ^ (row&7)
    __shared__ float sB0[256], sBres[3][256], sWout[256], sScale[3];
    __shared__ float souts[64];
    __shared__ int sidx[64];

    int t = blockIdx.x;
    if (t * 64 >= g_astart[CN]) return;
    int c = 0;
#pragma unroll
    for (int i = 0; i < CN - 1; i++) if (t * 64 >= g_astart[i + 1]) c = i + 1;

    int tid = threadIdx.x;
    int w = tid >> 5, lane = tid & 31;
    int g = lane >> 2, tig = lane & 3;
    int mat = lane >> 3, rowin = lane & 7;
    int wbase = w * 32;

    sB0[tid]      = b0[c * 256 + tid];
    sBres[0][tid] = bres[(c * 3 + 0) * 256 + tid];
    sBres[1][tid] = bres[(c * 3 + 1) * 256 + tid];
    sBres[2][tid] = bres[(c * 3 + 2) * 256 + tid];
    sWout[tid]    = Wout[c * 256 + tid];
    if (tid < 3)  sScale[tid] = scales[c * 3 + tid];
    if (tid < 64) { sidx[tid] = g_sorted[t * 64 + tid]; souts[tid] = 0.f; }
    __syncthreads();

    // stage encoding tile (64 x 32 halves) into hbuf, swizzled
    {
        int r = tid >> 2, cc = tid & 3;
        int j = sidx[r] & 0x7fffffff;   // pad slots (INT_MIN) -> point 0, compute wasted, store masked
        uint4 v = *reinterpret_cast<const uint4*>(&g_enc[(size_t)j * 16 + cc * 4]);
        *reinterpret_cast<uint4*>(&hbuf[r * 256 + ((cc ^ (r & 7)) << 3)]) = v;
    }
    __syncthreads();

    unsigned hb32 = (unsigned)__cvta_generic_to_shared(hbuf);
    unsigned* hbu = reinterpret_cast<unsigned*>(hbuf);

    float acc[4][4][4];
    float hres[4][4][4];

    // ---- layer 0: enc[64x32] @ W0[32x256] ----
#pragma unroll
    for (int mt = 0; mt < 4; mt++)
#pragma unroll
        for (int nt = 0; nt < 4; nt++)
#pragma unroll
            for (int e = 0; e < 4; e++) acc[mt][nt][e] = 0.f;
#pragma unroll
    for (int kc = 0; kc < 2; kc++) {
        unsigned af[4][4];
#pragma unroll
        for (int mt = 0; mt < 4; mt++) {
            int row = mt * 16 + ((mat & 1) << 3) + rowin;
            int cc  = (kc << 1) + (mat >> 1);
            ldmA(af[mt], hb32 + row * 512 + ((cc ^ (row & 7)) << 4));
        }
        uint2 bf[4];
#pragma unroll
        for (int nt = 0; nt < 4; nt++)
            bf[nt] = g_W0F[(((c * 2 + kc) * 8 + w) * 4 + nt) * 32 + lane];
#pragma unroll
        for (int mt = 0; mt < 4; mt++)
#pragma unroll
            for (int nt = 0; nt < 4; nt++)
                mma16816(acc[mt][nt], af[mt], bf[nt].x, bf[nt].y);
    }
#pragma unroll
    for (int mt = 0; mt < 4; mt++)
#pragma unroll
        for (int nt = 0; nt < 4; nt++) {
            int n0 = wbase + nt * 8 + tig * 2;
            hres[mt][nt][0] = fmaxf(acc[mt][nt][0] + sB0[n0], 0.f);
            hres[mt][nt][1] = fmaxf(acc[mt][nt][1] + sB0[n0 + 1], 0.f);
            hres[mt][nt][2] = fmaxf(acc[mt][nt][2] + sB0[n0], 0.f);
            hres[mt][nt][3] = fmaxf(acc[mt][nt][3] + sB0[n0 + 1], 0.f);
        }
    __syncthreads();   // all reads of enc tile done
#pragma unroll
    for (int mt = 0; mt < 4; mt++)
#pragma unroll
        for (int nt = 0; nt < 4; nt++) {
            int row0 = mt * 16 + g, row1 = row0 + 8;
            int ccw = (wbase >> 3) + nt;
            __half2 p0 = __floats2half2_rn(hres[mt][nt][0], hres[mt][nt][1]);
            __half2 p1 = __floats2half2_rn(hres[mt][nt][2], hres[mt][nt][3]);
            hbu[row0 * 128 + ((ccw ^ (row0 & 7)) << 2) + tig] = *(unsigned*)&p0;
            hbu[row1 * 128 + ((ccw ^ (row1 & 7)) << 2) + tig] = *(unsigned*)&p1;
        }
    __syncthreads();

    // ---- residual blocks ----
#pragma unroll
    for (int li = 0; li < 3; li++) {
#pragma unroll
        for (int mt = 0; mt < 4; mt++)
#pragma unroll
            for (int nt = 0; nt < 4; nt++)
#pragma unroll
                for (int e = 0; e < 4; e++) acc[mt][nt][e] = 0.f;
#pragma unroll
        for (int kc = 0; kc < 16; kc++) {
            unsigned af[4][4];
#pragma unroll
            for (int mt = 0; mt < 4; mt++) {
                int row = mt * 16 + ((mat & 1) << 3) + rowin;
                int cc  = (kc << 1) + (mat >> 1);
                ldmA(af[mt], hb32 + row * 512 + ((cc ^ (row & 7)) << 4));
            }
            uint2 bf[4];
#pragma unroll
            for (int nt = 0; nt < 4; nt++)
                bf[nt] = g_WrF[((((c * 3 + li) * 16 + kc) * 8 + w) * 4 + nt) * 32 + lane];
#pragma unroll
            for (int mt = 0; mt < 4; mt++)
#pragma unroll
                for (int nt = 0; nt < 4; nt++)
                    mma16816(acc[mt][nt], af[mt], bf[nt].x, bf[nt].y);
        }
        float sc = sScale[li];
#pragma unroll
        for (int mt = 0; mt < 4; mt++)
#pragma unroll
            for (int nt = 0; nt < 4; nt++) {
                int n0 = wbase + nt * 8 + tig * 2;
                hres[mt][nt][0] = sc * fmaxf(acc[mt][nt][0] + sBres[li][n0], 0.f) + hres[mt][nt][0];
                hres[mt][nt][1] = sc * fmaxf(acc[mt][nt][1] + sBres[li][n0 + 1], 0.f) + hres[mt][nt][1];
                hres[mt][nt][2] = sc * fmaxf(acc[mt][nt][2] + sBres[li][n0], 0.f) + hres[mt][nt][2];
                hres[mt][nt][3] = sc * fmaxf(acc[mt][nt][3] + sBres[li][n0 + 1], 0.f) + hres[mt][nt][3];
            }
        if (li < 2) {
            __syncthreads();
#pragma unroll
            for (int mt = 0; mt < 4; mt++)
#pragma unroll
                for (int nt = 0; nt < 4; nt++) {
                    int row0 = mt * 16 + g, row1 = row0 + 8;
                    int ccw = (wbase >> 3) + nt;
                    __half2 p0 = __floats2half2_rn(hres[mt][nt][0], hres[mt][nt][1]);
                    __half2 p1 = __floats2half2_rn(hres[mt][nt][2], hres[mt][nt][3]);
                    hbu[row0 * 128 + ((ccw ^ (row0 & 7)) << 2) + tig] = *(unsigned*)&p0;
                    hbu[row1 * 128 + ((ccw ^ (row1 & 7)) << 2) + tig] = *(unsigned*)&p1;
                }
            __syncthreads();
        }
    }

    // ---- output layer: out = h @ Wout + bout ----
#pragma unroll
    for (int mt = 0; mt < 4; mt++) {
        float sA = 0.f, sB2 = 0.f;
#pragma unroll
        for (int nt = 0; nt < 4; nt++) {
            int n0 = wbase + nt * 8 + tig * 2;
            sA  += hres[mt][nt][0] * sWout[n0] + hres[mt][nt][1] * sWout[n0 + 1];
            sB2 += hres[mt][nt][2] * sWout[n0] + hres[mt][nt][3] * sWout[n0 + 1];
        }
        sA  += __shfl_xor_sync(0xffffffffu, sA, 1);
        sA  += __shfl_xor_sync(0xffffffffu, sA, 2);
        sB2 += __shfl_xor_sync(0xffffffffu, sB2, 1);
        sB2 += __shfl_xor_sync(0xffffffffu, sB2, 2);
        if (tig == 0) {
            atomicAdd(&souts[mt * 16 + g], sA);
            atomicAdd(&souts[mt * 16 + 8 + g], sB2);
        }
    }
    __syncthreads();
    if (tid < 64) {
        int id = sidx[tid];
        if (id >= 0) out[id] = souts[tid] + bout[c];
    }
}

// ---------------- launch ----------------
extern "C" void kernel_launch(void* const* d_in, const int* in_sizes, int n_in,
                              void* d_out, int out_size) {
    const float* x      = (const float*)d_in[0];
    const int*   lid    = (const int*)d_in[1];
    const float* emb    = (const float*)d_in[2];
    const float* W0     = (const float*)d_in[3];
    const float* b0     = (const float*)d_in[4];
    const float* Wres   = (const float*)d_in[5];
    const float* bres   = (const float*)d_in[6];
    const float* scales = (const float*)d_in[7];
    const float* Wout   = (const float*)d_in[8];
    const float* bout   = (const float*)d_in[9];
    float* out = (float*)d_out;

    zero_kernel<<<1, 32>>>();
    hist_kernel<<<BN / 256, 256>>>(lid);
    starts_kernel<<<1, 1>>>();
    encode_kernel<<<NLEV * (BN / 256), 256>>>(x, emb);   // 4th launch -> ncu capture slot
    pad_kernel<<<(BN + 256 + 255) / 256, 256>>>();
    scatter_kernel<<<BN / 256, 256>>>(lid);
    prep_kernel<<<800, 256>>>(W0, Wres);
    mlp_kernel<<<BN / 64 + CN, 256>>>(b0, bres, scales, Wout, bout, out);
}